// round 2
// baseline (speedup 1.0000x reference)
#include <cuda_runtime.h>
#include <cuda_bf16.h>
#include <math.h>

#define NN  50000
#define EE  800000
#define INC 512
#define HH  64
#define OC  40
#define NL  64
#define NBLK ((NN + 1023) / 1024)   // 49 scan blocks

// ---------------- device scratch (static, no allocation) ----------------
__device__ float g_dinv[NN];
__device__ int   g_cnt[NN];
__device__ int   g_rowptr[NN + 1];
__device__ int   g_bsum[NBLK];
__device__ int   g_boff[NBLK];
__device__ int   g_fill[NN];
__device__ int   g_col[EE];
__device__ float g_val[EE];
__device__ float g_x0[NN * HH];
__device__ float g_hbuf[2][NN * HH];
__device__ int   g_is64;

// ---------------- preprocessing ----------------
__global__ void k_zero_cnt() {
    int i = blockIdx.x * blockDim.x + threadIdx.x;
    if (i < NN) g_cnt[i] = 0;
}

// Detect int64 vs int32 edge_index: int64 values < 2^31 -> odd words all 0.
__global__ void k_detect(const int* ei32) {
    if (threadIdx.x == 0 && blockIdx.x == 0) {
        int all0 = 1;
        for (int i = 0; i < 64; i++)
            if (ei32[2 * i + 1] != 0) all0 = 0;
        g_is64 = all0;
    }
}

__global__ void k_count(const void* eiv) {
    int e = blockIdx.x * blockDim.x + threadIdx.x;
    if (e >= EE) return;
    int d;
    if (g_is64) d = (int)((const long long*)eiv)[EE + e];
    else        d = ((const int*)eiv)[EE + e];
    atomicAdd(&g_cnt[d], 1);
}

// Phase A: per-block (1024 wide) exclusive scan, coalesced.
__global__ __launch_bounds__(1024) void k_scanA() {
    __shared__ int wsum[32];
    int t = threadIdx.x, b = blockIdx.x;
    int i = b * 1024 + t;
    int v = (i < NN) ? g_cnt[i] : 0;
    int lane = t & 31, wid = t >> 5;
    // warp inclusive scan
    int s = v;
#pragma unroll
    for (int o = 1; o < 32; o <<= 1) {
        int u = __shfl_up_sync(0xffffffffu, s, o);
        if (lane >= o) s += u;
    }
    if (lane == 31) wsum[wid] = s;
    __syncthreads();
    if (wid == 0) {
        int ws = (lane < 32) ? wsum[lane] : 0;
#pragma unroll
        for (int o = 1; o < 32; o <<= 1) {
            int u = __shfl_up_sync(0xffffffffu, ws, o);
            if (lane >= o) ws += u;
        }
        wsum[lane] = ws;
    }
    __syncthreads();
    int excl = s - v + (wid > 0 ? wsum[wid - 1] : 0);
    if (i < NN) g_rowptr[i] = excl;
    if (t == 1023) g_bsum[b] = excl + v;
}

// Phase B: scan 49 block sums (1 warp-ish block).
__global__ void k_scanB() {
    int t = threadIdx.x;  // 64 threads
    __shared__ int sh[64];
    sh[t] = (t < NBLK) ? g_bsum[t] : 0;
    __syncthreads();
    for (int o = 1; o < 64; o <<= 1) {
        int u = (t >= o) ? sh[t - o] : 0;
        __syncthreads();
        sh[t] += u;
        __syncthreads();
    }
    if (t < NBLK) g_boff[t] = sh[t] - g_bsum[t];  // exclusive
}

// Phase C: add offsets; compute dinv; zero fill; set rowptr[NN].
__global__ void k_scanC() {
    int i = blockIdx.x * blockDim.x + threadIdx.x;
    if (i < NN) {
        g_rowptr[i] += g_boff[i >> 10];
        g_dinv[i] = rsqrtf((float)(g_cnt[i] + 1));
        g_fill[i] = 0;
    }
    if (i == 0) g_rowptr[NN] = EE;
}

__global__ void k_fill(const void* eiv) {
    int e = blockIdx.x * blockDim.x + threadIdx.x;
    if (e >= EE) return;
    int s, d;
    if (g_is64) {
        const long long* ei = (const long long*)eiv;
        s = (int)ei[e];
        d = (int)ei[EE + e];
    } else {
        const int* ei = (const int*)eiv;
        s = ei[e];
        d = ei[EE + e];
    }
    int pos = g_rowptr[d] + atomicAdd(&g_fill[d], 1);
    g_col[pos] = s;
    g_val[pos] = g_dinv[s] * g_dinv[d];
}

// ---------------- lin1: h = relu(x @ W1 + b1), write x0 and hbuf[0] ----------------
__global__ __launch_bounds__(256) void k_lin1(const float* __restrict__ x,
                                              const float* __restrict__ w1,
                                              const float* __restrict__ b1) {
    __shared__ float xsT[32][257];
    __shared__ float ws[32 * 64];
    int t = threadIdx.x;
    int node0 = blockIdx.x * 256;

    float acc[64];
#pragma unroll
    for (int c = 0; c < 64; c++) acc[c] = 0.f;

    for (int kt = 0; kt < INC; kt += 32) {
        for (int i = t; i < 32 * 64; i += 256)
            ws[i] = w1[(kt + (i >> 6)) * 64 + (i & 63)];
        for (int i = t; i < 2048; i += 256) {
            int r = i >> 3, c4 = i & 7;
            int node = node0 + r;
            float4 v = make_float4(0.f, 0.f, 0.f, 0.f);
            if (node < NN)
                v = *(const float4*)&x[(size_t)node * INC + kt + c4 * 4];
            xsT[c4 * 4 + 0][r] = v.x;
            xsT[c4 * 4 + 1][r] = v.y;
            xsT[c4 * 4 + 2][r] = v.z;
            xsT[c4 * 4 + 3][r] = v.w;
        }
        __syncthreads();
#pragma unroll 4
        for (int k = 0; k < 32; k++) {
            float xv = xsT[k][t];
            const float4* wr = (const float4*)&ws[k * 64];
#pragma unroll
            for (int c4 = 0; c4 < 16; c4++) {
                float4 w4 = wr[c4];
                acc[c4 * 4 + 0] += xv * w4.x;
                acc[c4 * 4 + 1] += xv * w4.y;
                acc[c4 * 4 + 2] += xv * w4.z;
                acc[c4 * 4 + 3] += xv * w4.w;
            }
        }
        __syncthreads();
    }
    int node = node0 + t;
    if (node < NN) {
#pragma unroll
        for (int c = 0; c < 64; c++) {
            float v = fmaxf(acc[c] + b1[c], 0.f);
            g_x0[node * 64 + c] = v;
            g_hbuf[0][node * 64 + c] = v;
        }
    }
}

// ---------------- fused GCNII layer ----------------
// warp-per-node; statically unrolled padded gather for MLP; W in smem.
#define EDGE4(J)                                                             \
    {                                                                        \
        int s0 = __shfl_sync(0xffffffffu, cc, (J));                          \
        int s1 = __shfl_sync(0xffffffffu, cc, (J) + 1);                      \
        int s2 = __shfl_sync(0xffffffffu, cc, (J) + 2);                      \
        int s3 = __shfl_sync(0xffffffffu, cc, (J) + 3);                      \
        float w0 = __shfl_sync(0xffffffffu, vv, (J));                        \
        float w1 = __shfl_sync(0xffffffffu, vv, (J) + 1);                    \
        float w2 = __shfl_sync(0xffffffffu, vv, (J) + 2);                    \
        float w3 = __shfl_sync(0xffffffffu, vv, (J) + 3);                    \
        float2 h0 = *(const float2*)&hin[s0 * 64 + l2];                      \
        float2 h1 = *(const float2*)&hin[s1 * 64 + l2];                      \
        float2 h2 = *(const float2*)&hin[s2 * 64 + l2];                      \
        float2 h3 = *(const float2*)&hin[s3 * 64 + l2];                      \
        a0 += w0 * h0.x; a1 += w0 * h0.y;                                    \
        b0 += w1 * h1.x; b1 += w1 * h1.y;                                    \
        c0 += w2 * h2.x; c1 += w2 * h2.y;                                    \
        d0 += w3 * h3.x; d1 += w3 * h3.y;                                    \
    }

__global__ __launch_bounds__(256) void k_layer(const float* __restrict__ W,
                                               float beta, int p) {
    __shared__ float ws[64 * 64];
    __shared__ float zsm[8][64];
    int t = threadIdx.x, w = t >> 5, lane = t & 31;
    int l2 = lane * 2;
    for (int i = t; i < 4096; i += 256) ws[i] = W[i];
    __syncthreads();

    const float* __restrict__ hin = g_hbuf[p];
    float* __restrict__ hout = g_hbuf[p ^ 1];
    int warpG = blockIdx.x * 8 + w;
    int nW = gridDim.x * 8;

    for (int node = warpG; node < NN; node += nW) {
        float di = g_dinv[node];
        float2 hme = *(const float2*)&hin[node * 64 + l2];
        float a0 = di * di * hme.x;
        float a1 = di * di * hme.y;
        float b0 = 0.f, b1 = 0.f, c0 = 0.f, c1 = 0.f, d0 = 0.f, d1 = 0.f;
        int e0 = g_rowptr[node], e1 = g_rowptr[node + 1];
        for (int eb = e0; eb < e1; eb += 32) {
            int ee = eb + lane;
            bool ok = ee < e1;
            int cc = ok ? g_col[ee] : 0;
            float vv = ok ? g_val[ee] : 0.f;
            // first half-chunk (always; padded lanes contribute 0 via vv=0)
            EDGE4(0) EDGE4(4) EDGE4(8) EDGE4(12)
            if (eb + 16 < e1) {
                EDGE4(16) EDGE4(20) EDGE4(24) EDGE4(28)
            }
        }
        a0 += b0 + c0 + d0;
        a1 += b1 + c1 + d1;

        float2 x02 = *(const float2*)&g_x0[node * 64 + l2];
        float z0 = 0.5f * a0 + 0.5f * x02.x;
        float z1 = 0.5f * a1 + 0.5f * x02.y;
        *(float2*)&zsm[w][l2] = make_float2(z0, z1);
        __syncwarp();
        float s0 = 0.f, s1 = 0.f;
#pragma unroll
        for (int k = 0; k < 64; k++) {
            float zk = zsm[w][k];
            float2 w2 = *(const float2*)&ws[k * 64 + l2];
            s0 += zk * w2.x;
            s1 += zk * w2.y;
        }
        float ob = 1.f - beta;
        float o0 = fmaxf(ob * z0 + beta * s0, 0.f);
        float o1 = fmaxf(ob * z1 + beta * s1, 0.f);
        *(float2*)&hout[node * 64 + l2] = make_float2(o0, o1);
        __syncwarp();
    }
}

// ---------------- output: lin2 + log_softmax ----------------
__global__ __launch_bounds__(256) void k_out(const float* __restrict__ w2,
                                             const float* __restrict__ b2,
                                             float* __restrict__ out) {
    __shared__ float ws[64 * OC];
    __shared__ float bs[OC];
    __shared__ float zsm[8][64];
    int t = threadIdx.x, w = t >> 5, lane = t & 31;
    for (int i = t; i < 64 * OC; i += 256) ws[i] = w2[i];
    if (t < OC) bs[t] = b2[t];
    __syncthreads();

    const float* h = g_hbuf[0];  // NL even -> final state in buffer 0
    int warpG = blockIdx.x * 8 + w;
    int nW = gridDim.x * 8;

    for (int node = warpG; node < NN; node += nW) {
        float2 h2 = *(const float2*)&h[node * 64 + lane * 2];
        *(float2*)&zsm[w][lane * 2] = h2;
        __syncwarp();
        int c0 = lane;
        int c1 = lane + 32;
        float v0 = bs[c0];
        float v1 = (lane < 8) ? bs[c1] : 0.f;
#pragma unroll
        for (int k = 0; k < 64; k++) {
            float zk = zsm[w][k];
            v0 += zk * ws[k * OC + c0];
            if (lane < 8) v1 += zk * ws[k * OC + c1];
        }
        float m = v0;
        if (lane < 8) m = fmaxf(m, v1);
#pragma unroll
        for (int o = 16; o > 0; o >>= 1)
            m = fmaxf(m, __shfl_xor_sync(0xffffffffu, m, o));
        float se = expf(v0 - m) + ((lane < 8) ? expf(v1 - m) : 0.f);
#pragma unroll
        for (int o = 16; o > 0; o >>= 1)
            se += __shfl_xor_sync(0xffffffffu, se, o);
        float lse = m + logf(se);
        out[node * OC + c0] = v0 - lse;
        if (lane < 8) out[node * OC + c1] = v1 - lse;
        __syncwarp();
    }
}

// ---------------- launch ----------------
extern "C" void kernel_launch(void* const* d_in, const int* in_sizes, int n_in,
                              void* d_out, int out_size) {
    (void)in_sizes; (void)n_in; (void)out_size;
    const float* x  = (const float*)d_in[0];
    const void*  ei = d_in[1];
    const float* w1 = (const float*)d_in[2];
    const float* b1 = (const float*)d_in[3];
    const float* cw = (const float*)d_in[4];
    const float* w2 = (const float*)d_in[5];
    const float* b2 = (const float*)d_in[6];
    float* out = (float*)d_out;

    k_zero_cnt<<<(NN + 1023) / 1024, 1024>>>();
    k_detect<<<1, 32>>>((const int*)ei);
    k_count<<<(EE + 255) / 256, 256>>>(ei);
    k_scanA<<<NBLK, 1024>>>();
    k_scanB<<<1, 64>>>();
    k_scanC<<<(NN + 1023) / 1024, 1024>>>();
    k_fill<<<(EE + 255) / 256, 256>>>(ei);
    k_lin1<<<(NN + 255) / 256, 256>>>(x, w1, b1);

    for (int l = 0; l < NL; l++) {
        float beta = logf(1.0f / (float)(l + 1) + 1.0f);
        k_layer<<<148 * 8, 256>>>(cw + (size_t)l * HH * HH, beta, l & 1);
    }
    k_out<<<512, 256>>>(w2, b2, out);
}

// round 3
// speedup vs baseline: 1.4242x; 1.4242x over previous
#include <cuda_runtime.h>
#include <cuda_bf16.h>
#include <math.h>

#define NN  50000
#define EE  800000
#define INC 512
#define HH  64
#define OC  40
#define NL  64

// ---------------- device scratch (static, no allocation) ----------------
__device__ float g_dinv[NN];
__device__ int   g_cnt[NN];
__device__ int   g_rowptr[NN + 1];
__device__ int   g_fill[NN];
__device__ int   g_col[EE];
__device__ float g_val[EE];
__device__ float g_x0[NN * HH];
__device__ float g_hbuf[2][NN * HH];
__device__ int   g_is64;

// ---------------- lin1: h = relu(x @ W1 + b1) (launch #0) ----------------
__global__ __launch_bounds__(256) void k_lin1(const float* __restrict__ x,
                                              const float* __restrict__ w1,
                                              const float* __restrict__ b1) {
    __shared__ float xsT[32][257];
    __shared__ float ws[32 * 64];
    int t = threadIdx.x;
    int node0 = blockIdx.x * 256;

    float acc[64];
#pragma unroll
    for (int c = 0; c < 64; c++) acc[c] = 0.f;

    for (int kt = 0; kt < INC; kt += 32) {
        for (int i = t; i < 32 * 64; i += 256)
            ws[i] = w1[(kt + (i >> 6)) * 64 + (i & 63)];
        for (int i = t; i < 2048; i += 256) {
            int r = i >> 3, c4 = i & 7;
            int node = node0 + r;
            float4 v = make_float4(0.f, 0.f, 0.f, 0.f);
            if (node < NN)
                v = *(const float4*)&x[(size_t)node * INC + kt + c4 * 4];
            xsT[c4 * 4 + 0][r] = v.x;
            xsT[c4 * 4 + 1][r] = v.y;
            xsT[c4 * 4 + 2][r] = v.z;
            xsT[c4 * 4 + 3][r] = v.w;
        }
        __syncthreads();
#pragma unroll 4
        for (int k = 0; k < 32; k++) {
            float xv = xsT[k][t];
            const float4* wr = (const float4*)&ws[k * 64];
#pragma unroll
            for (int c4 = 0; c4 < 16; c4++) {
                float4 w4 = wr[c4];
                acc[c4 * 4 + 0] += xv * w4.x;
                acc[c4 * 4 + 1] += xv * w4.y;
                acc[c4 * 4 + 2] += xv * w4.z;
                acc[c4 * 4 + 3] += xv * w4.w;
            }
        }
        __syncthreads();
    }
    int node = node0 + t;
    if (node < NN) {
#pragma unroll
        for (int c = 0; c < 64; c++) {
            float v = fmaxf(acc[c] + b1[c], 0.f);
            g_x0[node * 64 + c] = v;
            g_hbuf[0][node * 64 + c] = v;
        }
    }
}

// ---------------- preprocessing ----------------
// launch #1: zero counts + detect int64 vs int32 (odd words of int64<2^31 are 0)
__global__ void k_zero_detect(const int* ei32) {
    int i = blockIdx.x * blockDim.x + threadIdx.x;
    if (i < NN) g_cnt[i] = 0;
    if (i == 0) {
        int all0 = 1;
        for (int j = 0; j < 64; j++)
            if (ei32[2 * j + 1] != 0) all0 = 0;
        g_is64 = all0;
    }
}

// launch #2
__global__ void k_count(const void* eiv) {
    int e = blockIdx.x * blockDim.x + threadIdx.x;
    if (e >= EE) return;
    int d;
    if (g_is64) d = (int)((const long long*)eiv)[EE + e];
    else        d = ((const int*)eiv)[EE + e];
    atomicAdd(&g_cnt[d], 1);
}

// launch #3: single-block coalesced scan over 50000 counts (+dinv, fill=0)
__global__ __launch_bounds__(1024) void k_scan() {
    __shared__ int wsum[32];
    __shared__ int chunk_total;
    int t = threadIdx.x, lane = t & 31, wid = t >> 5;
    int running = 0;
    for (int c = 0; c < (NN + 1023) / 1024; c++) {
        int i = c * 1024 + t;
        int v = (i < NN) ? g_cnt[i] : 0;
        int s = v;
#pragma unroll
        for (int o = 1; o < 32; o <<= 1) {
            int u = __shfl_up_sync(0xffffffffu, s, o);
            if (lane >= o) s += u;
        }
        if (lane == 31) wsum[wid] = s;
        __syncthreads();
        if (wid == 0) {
            int ws = wsum[lane];
#pragma unroll
            for (int o = 1; o < 32; o <<= 1) {
                int u = __shfl_up_sync(0xffffffffu, ws, o);
                if (lane >= o) ws += u;
            }
            wsum[lane] = ws;
            if (lane == 31) chunk_total = ws;
        }
        __syncthreads();
        int excl = running + s - v + (wid > 0 ? wsum[wid - 1] : 0);
        if (i < NN) {
            g_rowptr[i] = excl;
            g_dinv[i] = rsqrtf((float)(v + 1));
            g_fill[i] = 0;
        }
        running += chunk_total;
        __syncthreads();
    }
    if (t == 0) g_rowptr[NN] = EE;
}

// launch #4
__global__ void k_fill(const void* eiv) {
    int e = blockIdx.x * blockDim.x + threadIdx.x;
    if (e >= EE) return;
    int s, d;
    if (g_is64) {
        const long long* ei = (const long long*)eiv;
        s = (int)ei[e];
        d = (int)ei[EE + e];
    } else {
        const int* ei = (const int*)eiv;
        s = ei[e];
        d = ei[EE + e];
    }
    int pos = g_rowptr[d] + atomicAdd(&g_fill[d], 1);
    g_col[pos] = s;
    g_val[pos] = g_dinv[s] * g_dinv[d];
}

// ---------------- fused GCNII layer (launch #5+) ----------------
// warp handles 4 nodes: exact gather (4-wide unroll), z kept in regs,
// transposed float4 staging, shared-W GEMM amortized over 4 nodes.
__global__ __launch_bounds__(256) void k_layer(const float* __restrict__ W,
                                               float beta, int p) {
    __shared__ float ws[64 * 64];
    __shared__ float4 zq[8][64];
    int t = threadIdx.x, w = t >> 5, lane = t & 31;
    int l2 = lane * 2;
    for (int i = t; i < 4096; i += 256) ws[i] = W[i];
    __syncthreads();

    const float* __restrict__ hin = g_hbuf[p];
    float* __restrict__ hout = g_hbuf[p ^ 1];
    int warpG = blockIdx.x * 8 + w;
    int nW = gridDim.x * 8;
    float ob = 1.f - beta;

    for (int base = warpG * 4; base < NN; base += nW * 4) {
        float z[4][2];
#pragma unroll
        for (int q = 0; q < 4; q++) {
            int node = base + q;
            if (node >= NN) { z[q][0] = 0.f; z[q][1] = 0.f; continue; }
            float di = g_dinv[node];
            float2 hme = *(const float2*)&hin[node * 64 + l2];
            float a0 = di * di * hme.x;
            float a1 = di * di * hme.y;
            float b0 = 0.f, b1 = 0.f, c0 = 0.f, c1 = 0.f, d0 = 0.f, d1 = 0.f;
            int e0 = g_rowptr[node], e1 = g_rowptr[node + 1];
            for (int eb = e0; eb < e1; eb += 32) {
                int ee = eb + lane;
                bool okl = ee < e1;
                int cc = okl ? g_col[ee] : 0;
                float vv = okl ? g_val[ee] : 0.f;
                int cn = min(32, e1 - eb);
                int j = 0;
                for (; j + 3 < cn; j += 4) {
                    int s0 = __shfl_sync(0xffffffffu, cc, j);
                    int s1 = __shfl_sync(0xffffffffu, cc, j + 1);
                    int s2 = __shfl_sync(0xffffffffu, cc, j + 2);
                    int s3 = __shfl_sync(0xffffffffu, cc, j + 3);
                    float w0 = __shfl_sync(0xffffffffu, vv, j);
                    float w1 = __shfl_sync(0xffffffffu, vv, j + 1);
                    float w2 = __shfl_sync(0xffffffffu, vv, j + 2);
                    float w3 = __shfl_sync(0xffffffffu, vv, j + 3);
                    float2 h0 = *(const float2*)&hin[s0 * 64 + l2];
                    float2 h1 = *(const float2*)&hin[s1 * 64 + l2];
                    float2 h2 = *(const float2*)&hin[s2 * 64 + l2];
                    float2 h3 = *(const float2*)&hin[s3 * 64 + l2];
                    a0 += w0 * h0.x; a1 += w0 * h0.y;
                    b0 += w1 * h1.x; b1 += w1 * h1.y;
                    c0 += w2 * h2.x; c1 += w2 * h2.y;
                    d0 += w3 * h3.x; d1 += w3 * h3.y;
                }
                for (; j < cn; j++) {
                    int s0 = __shfl_sync(0xffffffffu, cc, j);
                    float w0 = __shfl_sync(0xffffffffu, vv, j);
                    float2 h0 = *(const float2*)&hin[s0 * 64 + l2];
                    a0 += w0 * h0.x; a1 += w0 * h0.y;
                }
            }
            a0 += b0 + c0 + d0;
            a1 += b1 + c1 + d1;
            float2 x02 = *(const float2*)&g_x0[node * 64 + l2];
            z[q][0] = 0.5f * a0 + 0.5f * x02.x;
            z[q][1] = 0.5f * a1 + 0.5f * x02.y;
        }
        // stage z transposed: zq[k] = {zA[k], zB[k], zC[k], zD[k]}
        zq[w][l2]     = make_float4(z[0][0], z[1][0], z[2][0], z[3][0]);
        zq[w][l2 + 1] = make_float4(z[0][1], z[1][1], z[2][1], z[3][1]);
        __syncwarp();

        float4 s0 = make_float4(0.f, 0.f, 0.f, 0.f);  // col l2, nodes A..D
        float4 s1 = make_float4(0.f, 0.f, 0.f, 0.f);  // col l2+1
#pragma unroll
        for (int k = 0; k < 64; k++) {
            float4 zk = zq[w][k];
            float2 wk = *(const float2*)&ws[k * 64 + l2];
            s0.x += zk.x * wk.x; s0.y += zk.y * wk.x;
            s0.z += zk.z * wk.x; s0.w += zk.w * wk.x;
            s1.x += zk.x * wk.y; s1.y += zk.y * wk.y;
            s1.z += zk.z * wk.y; s1.w += zk.w * wk.y;
        }
        float sc0[4] = {s0.x, s0.y, s0.z, s0.w};
        float sc1[4] = {s1.x, s1.y, s1.z, s1.w};
#pragma unroll
        for (int q = 0; q < 4; q++) {
            int node = base + q;
            if (node < NN) {
                float o0 = fmaxf(ob * z[q][0] + beta * sc0[q], 0.f);
                float o1 = fmaxf(ob * z[q][1] + beta * sc1[q], 0.f);
                *(float2*)&hout[node * 64 + l2] = make_float2(o0, o1);
            }
        }
        __syncwarp();
    }
}

// ---------------- output: lin2 + log_softmax ----------------
__global__ __launch_bounds__(256) void k_out(const float* __restrict__ w2,
                                             const float* __restrict__ b2,
                                             float* __restrict__ out) {
    __shared__ float ws[64 * OC];
    __shared__ float bs[OC];
    __shared__ float zsm[8][64];
    int t = threadIdx.x, w = t >> 5, lane = t & 31;
    for (int i = t; i < 64 * OC; i += 256) ws[i] = w2[i];
    if (t < OC) bs[t] = b2[t];
    __syncthreads();

    const float* h = g_hbuf[0];  // NL even -> final state in buffer 0
    int warpG = blockIdx.x * 8 + w;
    int nW = gridDim.x * 8;

    for (int node = warpG; node < NN; node += nW) {
        float2 h2 = *(const float2*)&h[node * 64 + lane * 2];
        *(float2*)&zsm[w][lane * 2] = h2;
        __syncwarp();
        int c0 = lane;
        int c1 = lane + 32;
        float v0 = bs[c0];
        float v1 = (lane < 8) ? bs[c1] : 0.f;
#pragma unroll
        for (int k = 0; k < 64; k++) {
            float zk = zsm[w][k];
            v0 += zk * ws[k * OC + c0];
            if (lane < 8) v1 += zk * ws[k * OC + c1];
        }
        float m = v0;
        if (lane < 8) m = fmaxf(m, v1);
#pragma unroll
        for (int o = 16; o > 0; o >>= 1)
            m = fmaxf(m, __shfl_xor_sync(0xffffffffu, m, o));
        float se = expf(v0 - m) + ((lane < 8) ? expf(v1 - m) : 0.f);
#pragma unroll
        for (int o = 16; o > 0; o >>= 1)
            se += __shfl_xor_sync(0xffffffffu, se, o);
        float lse = m + logf(se);
        out[node * OC + c0] = v0 - lse;
        if (lane < 8) out[node * OC + c1] = v1 - lse;
        __syncwarp();
    }
}

// ---------------- launch ----------------
extern "C" void kernel_launch(void* const* d_in, const int* in_sizes, int n_in,
                              void* d_out, int out_size) {
    (void)in_sizes; (void)n_in; (void)out_size;
    const float* x  = (const float*)d_in[0];
    const void*  ei = d_in[1];
    const float* w1 = (const float*)d_in[2];
    const float* b1 = (const float*)d_in[3];
    const float* cw = (const float*)d_in[4];
    const float* w2 = (const float*)d_in[5];
    const float* b2 = (const float*)d_in[6];
    float* out = (float*)d_out;

    k_lin1<<<(NN + 255) / 256, 256>>>(x, w1, b1);               // #0
    k_zero_detect<<<(NN + 1023) / 1024, 1024>>>((const int*)ei); // #1
    k_count<<<(EE + 255) / 256, 256>>>(ei);                      // #2
    k_scan<<<1, 1024>>>();                                       // #3
    k_fill<<<(EE + 255) / 256, 256>>>(ei);                       // #4

    for (int l = 0; l < NL; l++) {                               // #5..#68
        float beta = logf(1.0f / (float)(l + 1) + 1.0f);
        k_layer<<<148 * 8, 256>>>(cw + (size_t)l * HH * HH, beta, l & 1);
    }
    k_out<<<512, 256>>>(w2, b2, out);
}